// round 9
// baseline (speedup 1.0000x reference)
#include <cuda_runtime.h>
#include <cuda_fp16.h>
#include <cstdint>

// ScorePredictor: score[e] = dot(x[src[e]], x[dst[e]])
// x: [N, 64] fp32, src/dst: [E] int32 or int64 (runtime-detected).
//
// R9: main kernel is pinned at the chip LTS byte cap (~6300 B/cyc):
// 345MB of L2 traffic in 27.2us = 12.7TB/s. Only remaining slack is wave
// quantization (9766 blocks = 9.43 waves of 1036 -> ~40%-full tail wave).
// Switch to a grid-stride loop with exactly one resident wave (148*7 blocks)
// so all blocks finish within ~1 iteration of each other.

static constexpr int D_FEAT = 64;
static constexpr int MAX_NODES = 262144;
static constexpr int THREADS = 256;
static constexpr int EPG = 4;             // edges per 8-lane group
static constexpr int GROUPS_PER_BLOCK = THREADS / 8;
static constexpr int EDGES_PER_BLOCK = GROUPS_PER_BLOCK * EPG;  // 128
static constexpr int RESIDENT_BLOCKS = 148 * 7;  // one full wave on B200/B300

__device__ int g_idx_is_64 = 0;
__device__ __align__(256) __half g_xh[(size_t)MAX_NODES * D_FEAT];  // 32MB scratch

// --- fp32 -> fp16 conversion (8 floats/thread) + dtype detection. ---
__global__ __launch_bounds__(THREADS)
void convert_kernel(const float4* __restrict__ x4, int n8,
                    const unsigned int* __restrict__ idx_words)
{
    int i = blockIdx.x * THREADS + threadIdx.x;
    if (i == 0) {
        // int64 (LE, values < 2^31) => all odd 32-bit words zero.
        int is64 = 1;
        #pragma unroll
        for (int k = 0; k < 32; k++)
            if (idx_words[2 * k + 1] != 0u) { is64 = 0; break; }
        g_idx_is_64 = is64;
    }
    if (i >= n8) return;
    float4 v0 = x4[2 * i + 0];
    float4 v1 = x4[2 * i + 1];
    __half2 h0 = __floats2half2_rn(v0.x, v0.y);
    __half2 h1 = __floats2half2_rn(v0.z, v0.w);
    __half2 h2 = __floats2half2_rn(v1.x, v1.y);
    __half2 h3 = __floats2half2_rn(v1.z, v1.w);
    uint4 p;
    p.x = *reinterpret_cast<unsigned*>(&h0);
    p.y = *reinterpret_cast<unsigned*>(&h1);
    p.z = *reinterpret_cast<unsigned*>(&h2);
    p.w = *reinterpret_cast<unsigned*>(&h3);
    reinterpret_cast<uint4*>(g_xh)[i] = p;
}

__device__ __forceinline__ float dot16(const uint4& a, const uint4& b)
{
    float sum = 0.0f;
    const unsigned* ap = &a.x;
    const unsigned* bp = &b.x;
    #pragma unroll
    for (int j = 0; j < 4; j++) {
        __half2 ha = *reinterpret_cast<const __half2*>(&ap[j]);
        __half2 hb = *reinterpret_cast<const __half2*>(&bp[j]);
        float2 fa = __half22float2(ha);
        float2 fb = __half22float2(hb);
        sum = fmaf(fa.x, fb.x, sum);
        sum = fmaf(fa.y, fb.y, sum);
    }
    return sum;
}

// Grid-stride over edge tiles. 8-lane group handles 4 edges per iteration;
// lanes 0-3 load src indices, lanes 4-7 dst; all lanes always participate
// (clamped) so full-warp shuffles are safe.
__global__ __launch_bounds__(THREADS, 7)
void edge_dot_kernel(const void* __restrict__ src_raw,
                     const void* __restrict__ dst_raw,
                     float* __restrict__ out,
                     int n_edges, int n_tiles)
{
    int lane   = threadIdx.x & 7;
    int gro    = threadIdx.x >> 3;             // group within block
    int elast  = n_edges - 1;
    int is64   = g_idx_is_64;                  // uniform
    const uint4* xh4 = reinterpret_cast<const uint4*>(g_xh);

    for (int tile = blockIdx.x; tile < n_tiles; tile += gridDim.x) {
        int ebase = tile * EDGES_PER_BLOCK + gro * EPG;

        // One index load per lane.
        int esub = ebase + (lane & 3);
        esub = esub < elast ? esub : elast;
        unsigned myidx;
        if (is64) {
            const unsigned long long* p = (lane < 4)
                ? (const unsigned long long*)src_raw
                : (const unsigned long long*)dst_raw;
            myidx = (unsigned)p[esub];
        } else {
            const unsigned* p = (lane < 4) ? (const unsigned*)src_raw
                                           : (const unsigned*)dst_raw;
            myidx = p[esub];
        }

        // Distribute indices, issue all 8 gathers back-to-back (MLP=8).
        uint4 a[EPG], b[EPG];
        #pragma unroll
        for (int k = 0; k < EPG; k++) {
            unsigned s = __shfl_sync(0xFFFFFFFFu, myidx, k, 8);
            unsigned d = __shfl_sync(0xFFFFFFFFu, myidx, 4 + k, 8);
            a[k] = xh4[s * 8u + lane];
            b[k] = xh4[d * 8u + lane];
        }

        float sum[EPG];
        #pragma unroll
        for (int k = 0; k < EPG; k++)
            sum[k] = dot16(a[k], b[k]);

        // Butterfly reduce: every lane ends with all 4 group totals.
        #pragma unroll
        for (int off = 4; off >= 1; off >>= 1) {
            #pragma unroll
            for (int k = 0; k < EPG; k++)
                sum[k] += __shfl_xor_sync(0xFFFFFFFFu, sum[k], off, 8);
        }

        // Coalesced store: lanes 0-3 write 4 consecutive floats.
        float v = (lane & 2) ? ((lane & 1) ? sum[3] : sum[2])
                             : ((lane & 1) ? sum[1] : sum[0]);
        int eo = ebase + (lane & 3);
        if (lane < 4 && eo < n_edges) out[eo] = v;
    }
}

extern "C" void kernel_launch(void* const* d_in, const int* in_sizes, int n_in,
                              void* d_out, int out_size)
{
    // x = largest input; other two are index arrays (dot is symmetric).
    int xi = 0;
    for (int i = 1; i < n_in; i++)
        if (in_sizes[i] > in_sizes[xi]) xi = i;
    int i1 = -1, i2 = -1;
    for (int i = 0; i < n_in; i++) {
        if (i == xi) continue;
        if (i1 < 0) i1 = i; else i2 = i;
    }

    const float4* x4  = (const float4*)d_in[xi];
    const void*   src = d_in[i1];
    const void*   dst = d_in[i2];
    float*        out = (float*)d_out;

    int n_edges = in_sizes[i1];
    int n8      = in_sizes[xi] / 8;   // 8-float chunks of x

    convert_kernel<<<(n8 + THREADS - 1) / THREADS, THREADS>>>(
        x4, n8, (const unsigned int*)src);

    int n_tiles = (n_edges + EDGES_PER_BLOCK - 1) / EDGES_PER_BLOCK;
    int blocks = n_tiles < RESIDENT_BLOCKS ? n_tiles : RESIDENT_BLOCKS;
    edge_dot_kernel<<<blocks, THREADS>>>(src, dst, out, n_edges, n_tiles);
}